// round 7
// baseline (speedup 1.0000x reference)
#include <cuda_runtime.h>
#include <math.h>

// Problem shape (fixed for this benchmark instance)
#define BB 16
#define TT 2048
#define DD 1024
#define NROW (BB*TT)

// Block-role partition of the single uber grid
#define AB 4096            // alphas blocks (8 rows each, batch-major)
#define SBK BB             // scan blocks
#define GOFF (AB + SBK)    // gather blocks start here
#define NBLK (GOFF + NROW) // total blocks

// Scratch (device globals; no allocation allowed)
__device__ float  g_alphas[NROW];
__device__ float4 g_events[NROW];   // {curF, residF, t_bits, pad} per fire, packed
__device__ int    g_nf[BB];
__device__ int    g_cnt [BB * 32];  // one counter per 128B line
__device__ int    g_flag[BB * 32];  // one flag per 128B line

__global__ void k_reset() {
    int i = threadIdx.x;
    if (i < BB) { g_cnt[i * 32] = 0; g_flag[i * 32] = 0; }
}

__global__ void k_uber(const float* __restrict__ hs,
                       const float* __restrict__ mask,
                       const float* __restrict__ w,
                       const float* __restrict__ bias,
                       float* __restrict__ out,
                       float* __restrict__ omask) {
    __shared__ float  s_al[TT];      // 8 KB (scan role)
    __shared__ double s_part[256];   // 2 KB (scan role)
    __shared__ int    s_len;

    const int bid = blockIdx.x;
    const int tid = threadIdx.x;

    // ================= role 1: alphas =================
    if (bid < AB) {
        int row  = bid * 8 + (tid >> 5);     // (b,t) flat row
        int lane = tid & 31;

        const float4* r4 = reinterpret_cast<const float4*>(hs + (size_t)row * DD);
        const float4* w4 = reinterpret_cast<const float4*>(w);

        float acc = 0.0f;
#pragma unroll
        for (int i = 0; i < 8; i++) {
            float4 h  = r4[lane + 32 * i];
            float4 ww = __ldg(&w4[lane + 32 * i]);
            acc = fmaf(h.x, ww.x, acc);
            acc = fmaf(h.y, ww.y, acc);
            acc = fmaf(h.z, ww.z, acc);
            acc = fmaf(h.w, ww.w, acc);
        }
#pragma unroll
        for (int o = 16; o > 0; o >>= 1)
            acc += __shfl_down_sync(0xffffffffu, acc, o);

        if (lane == 0) {
            float x = acc + bias[0];
            float s = 1.0f / (1.0f + expf(-x));
            g_alphas[row] = s * mask[row];
        }
        __syncthreads();
        if (tid == 0) {
            __threadfence();
            atomicAdd(&g_cnt[(bid >> 8) * 32], 1);   // batch = bid/256
        }
        return;
    }

    // ================= role 2: scan (+ lens + mask) =================
    if (bid < GOFF) {
        int b = bid - AB;

        if (tid == 0) {
            volatile int* c = &g_cnt[b * 32];
            while (*c != 256) __nanosleep(128);
            __threadfence();
        }
        __syncthreads();

        // stage this batch's alphas into smem + per-thread partial sums
        const float4* al4 = reinterpret_cast<const float4*>(g_alphas + b * TT);
        float4* s4 = reinterpret_cast<float4*>(s_al);
        double psum = 0.0;
#pragma unroll
        for (int i = 0; i < 2; i++) {
            int idx = tid + i * 256;
            float4 v = al4[idx];
            s4[idx] = v;
            psum += (double)v.x + v.y + v.z + v.w;
        }
        s_part[tid] = psum;
        __syncthreads();

        int wid = tid >> 5;
        if (wid == 0) {
            if (tid == 0) {
                // ---- serial integrate-and-fire scan (bit-identical ops) ----
                //   s = integ + a; fire = s > 0.95f;
                //   cur = fire ? (1-integ) : a; integ = fire ? s-1.0f : s
                float4* ev = g_events + b * TT;
                float integ = 0.0f;
                int nf = 0;
                float4 p = s4[0];
                for (int t0 = 0; t0 < TT; t0 += 4) {
                    float buf[4];
                    buf[0] = p.x; buf[1] = p.y; buf[2] = p.z; buf[3] = p.w;
                    if (t0 + 4 < TT) p = s4[(t0 >> 2) + 1];
#pragma unroll
                    for (int j = 0; j < 4; j++) {
                        float a = buf[j];
                        float dist = 1.0f - integ;      // off critical path
                        float s = integ + a;            // FADD — critical
                        bool fire = (s > 0.95f);        // FSETP — critical
                        float4 e;
                        e.x = dist;                     // cur at fire
                        e.y = a - dist;                 // residual to next segment
                        e.z = __int_as_float(t0 + j);   // fire time index
                        e.w = 0.0f;
                        ev[nf] = e;                     // unconditional STG.128
                        nf += fire ? 1 : 0;
                        integ = fire ? (s - 1.0f) : s;  // FSEL — critical
                    }
                }
                g_nf[b] = nf;
            }
        } else {
            if (wid == 1) {
                int lane = tid & 31;
                double r = s_part[lane]       + s_part[lane + 32]
                         + s_part[lane + 64]  + s_part[lane + 96]
                         + s_part[lane + 128] + s_part[lane + 160]
                         + s_part[lane + 192] + s_part[lane + 224];
#pragma unroll
                for (int o = 16; o > 0; o >>= 1)
                    r += __shfl_down_sync(0xffffffffu, r, o);
                if (lane == 0) {
                    float fsum = (float)r;
                    s_len = (int)rintf(fsum);   // round-half-to-even like jnp.round
                }
            }
            // warps 1-7 sync among themselves; write mask while warp 0 scans
            asm volatile("bar.sync 1, 224;" ::: "memory");
            int len = s_len;
            float4* om4 = reinterpret_cast<float4*>(omask + b * TT);
            for (int i = tid - 32; i < TT / 4; i += 224) {
                int k = i * 4;
                float4 m;
                m.x = (k + 0 < len) ? 1.0f : 0.0f;
                m.y = (k + 1 < len) ? 1.0f : 0.0f;
                m.z = (k + 2 < len) ? 1.0f : 0.0f;
                m.w = (k + 3 < len) ? 1.0f : 0.0f;
                om4[i] = m;
            }
        }
        __syncthreads();
        if (tid == 0) {
            __threadfence();
            atomicExch(&g_flag[b * 32], 1);
        }
        return;
    }

    // ================= role 3: gather =================
    {
        int g = bid - GOFF;
        int b = g >> 11;           // g / TT
        int k = g & (TT - 1);      // g % TT

        if (tid == 0) {
            volatile int* f = &g_flag[b * 32];
            while (*f == 0) __nanosleep(128);
            __threadfence();
        }
        __syncthreads();

        float4* orow = reinterpret_cast<float4*>(out + ((size_t)(b * TT + k)) * DD);

        if (k >= g_nf[b]) {
            orow[tid] = make_float4(0.f, 0.f, 0.f, 0.f);
            return;
        }

        const int base = b * TT;
        float4 evk = g_events[base + k];
        int tend = __float_as_int(evk.z);

        float4 acc = make_float4(0.f, 0.f, 0.f, 0.f);
        int tprev = -1;

        if (k > 0) {
            float4 evp = g_events[base + k - 1];
            tprev = __float_as_int(evp.z);
            float r = evp.y;   // residual carried from previous fire row
            const float4* h = reinterpret_cast<const float4*>(hs + ((size_t)(base + tprev)) * DD);
            float4 v = h[tid];
            acc.x = r * v.x; acc.y = r * v.y; acc.z = r * v.z; acc.w = r * v.w;
        }

        // interior rows: coefficient == alpha
        for (int t = tprev + 1; t < tend; t++) {
            float c = g_alphas[base + t];
            const float4* h = reinterpret_cast<const float4*>(hs + ((size_t)(base + t)) * DD);
            float4 v = h[tid];
            acc.x = fmaf(c, v.x, acc.x);
            acc.y = fmaf(c, v.y, acc.y);
            acc.z = fmaf(c, v.z, acc.z);
            acc.w = fmaf(c, v.w, acc.w);
        }

        // fire row itself: coefficient == dist_completion
        {
            float c = evk.x;
            const float4* h = reinterpret_cast<const float4*>(hs + ((size_t)(base + tend)) * DD);
            float4 v = h[tid];
            acc.x = fmaf(c, v.x, acc.x);
            acc.y = fmaf(c, v.y, acc.y);
            acc.z = fmaf(c, v.z, acc.z);
            acc.w = fmaf(c, v.w, acc.w);
        }

        orow[tid] = acc;
    }
}

extern "C" void kernel_launch(void* const* d_in, const int* in_sizes, int n_in,
                              void* d_out, int out_size) {
    const float* hs   = (const float*)d_in[0];   // [B,T,D]
    const float* mask = (const float*)d_in[1];   // [B,1,T]
    const float* w    = (const float*)d_in[2];   // [D]
    const float* bias = (const float*)d_in[3];   // scalar

    float* out   = (float*)d_out;                           // [B,T,D]
    float* omask = (float*)d_out + (size_t)BB * TT * DD;    // [B,1,T] as 0/1 floats

    k_reset<<<1, 32>>>();
    k_uber<<<NBLK, 256>>>(hs, mask, w, bias, out, omask);
}

// round 8
// speedup vs baseline: 1.8195x; 1.8195x over previous
#include <cuda_runtime.h>
#include <math.h>

// Problem shape (fixed for this benchmark instance)
#define BB 16
#define TT 2048
#define DD 1024
#define NROW (BB*TT)
#define KCH 8              // output rows per gather block

// Scratch (device globals; no allocation allowed)
__device__ float  g_alphas[NROW];
__device__ float2 g_ev[NROW];   // {dist(=cur at fire), t_as_int_bits} per fire, packed
__device__ int    g_nf[BB];

// ---------------- Phase 1: alphas[b,t] = sigmoid(hs[b,t,:].w + bias) * mask[b,t]
__global__ void k_alphas(const float* __restrict__ hs,
                         const float* __restrict__ mask,
                         const float* __restrict__ w,
                         const float* __restrict__ bias) {
    int warp = (blockIdx.x * blockDim.x + threadIdx.x) >> 5;
    int lane = threadIdx.x & 31;
    if (warp >= NROW) return;

    const float4* row = reinterpret_cast<const float4*>(hs + (size_t)warp * DD);
    const float4* w4  = reinterpret_cast<const float4*>(w);

    float acc = 0.0f;
#pragma unroll
    for (int i = 0; i < 8; i++) {
        float4 h  = row[lane + 32 * i];
        float4 ww = __ldg(&w4[lane + 32 * i]);
        acc = fmaf(h.x, ww.x, acc);
        acc = fmaf(h.y, ww.y, acc);
        acc = fmaf(h.z, ww.z, acc);
        acc = fmaf(h.w, ww.w, acc);
    }
#pragma unroll
    for (int o = 16; o > 0; o >>= 1)
        acc += __shfl_down_sync(0xffffffffu, acc, o);

    if (lane == 0) {
        float x = acc + bias[0];
        float s = 1.0f / (1.0f + expf(-x));
        g_alphas[warp] = s * mask[warp];
    }
}

// ---------------- Phase 2 (fused): stage alphas to smem, serial scan (warp 0),
// lens + mask (warps 1-7, concurrent), compact event flush.
// Fire arithmetic bit-identical to the reference:
//   s = integ + a; fire = s > 0.95f;
//   cur = fire ? (1 - integ) : a; integ = fire ? s - 1.0f : s  (Sterbenz-exact)
__global__ void k_scan(float* __restrict__ omask) {
    __shared__ float  s_al[TT];      // 8 KB
    __shared__ float2 s_ev[TT];      // 16 KB
    __shared__ double s_part[256];   // 2 KB
    __shared__ int    s_nf;
    __shared__ int    s_len;

    int b   = blockIdx.x;
    int tid = threadIdx.x;
    int wid = tid >> 5;

    // Cooperative stage: 2048 floats = 512 float4, 2 per thread + partial sums.
    const float4* al4 = reinterpret_cast<const float4*>(g_alphas + b * TT);
    float4* s4 = reinterpret_cast<float4*>(s_al);
    double psum = 0.0;
#pragma unroll
    for (int i = 0; i < 2; i++) {
        int idx = tid + i * 256;
        float4 v = al4[idx];
        s4[idx] = v;
        psum += (double)v.x + v.y + v.z + v.w;
    }
    s_part[tid] = psum;
    __syncthreads();

    if (wid == 0) {
        if (tid == 0) {
            // -------- serial integrate-and-fire scan (from smem) --------
            float integ = 0.0f;
            int nf = 0;
            float4 p = s4[0];
            for (int t0 = 0; t0 < TT; t0 += 4) {
                float buf[4];
                buf[0] = p.x; buf[1] = p.y; buf[2] = p.z; buf[3] = p.w;
                if (t0 + 4 < TT) p = s4[(t0 >> 2) + 1];
#pragma unroll
                for (int j = 0; j < 4; j++) {
                    float a = buf[j];
                    float dist = 1.0f - integ;      // off critical path
                    float s = integ + a;            // FADD — critical
                    bool fire = (s > 0.95f);        // FSETP — critical
                    float2 e;
                    e.x = dist;                     // cur at fire
                    e.y = __int_as_float(t0 + j);   // fire time index
                    s_ev[nf] = e;                   // unconditional STS.64
                    nf += fire ? 1 : 0;
                    integ = fire ? (s - 1.0f) : s;  // FSEL — critical
                }
            }
            s_nf = nf;
        }
    } else {
        if (wid == 1) {
            // -------- length reduction (concurrent with scan) --------
            int lane = tid & 31;
            double r = s_part[lane]       + s_part[lane + 32]
                     + s_part[lane + 64]  + s_part[lane + 96]
                     + s_part[lane + 128] + s_part[lane + 160]
                     + s_part[lane + 192] + s_part[lane + 224];
#pragma unroll
            for (int o = 16; o > 0; o >>= 1)
                r += __shfl_down_sync(0xffffffffu, r, o);
            if (lane == 0) {
                float fsum = (float)r;
                s_len = (int)rintf(fsum);   // round-half-to-even like jnp.round
            }
        }
        // warps 1-7 sync among themselves; write mask while warp 0 scans
        asm volatile("bar.sync 1, 224;" ::: "memory");
        int len = s_len;
        float4* om4 = reinterpret_cast<float4*>(omask + b * TT);
        for (int i = tid - 32; i < TT / 4; i += 224) {
            int k = i * 4;
            float4 m;
            m.x = (k + 0 < len) ? 1.0f : 0.0f;
            m.y = (k + 1 < len) ? 1.0f : 0.0f;
            m.z = (k + 2 < len) ? 1.0f : 0.0f;
            m.w = (k + 3 < len) ? 1.0f : 0.0f;
            om4[i] = m;
        }
    }
    __syncthreads();

    // -------- coalesced event flush --------
    int nf = s_nf;
    float2* ev = g_ev + b * TT;
    for (int i = tid; i < nf; i += 256)
        ev[i] = s_ev[i];
    if (tid == 0) g_nf[b] = nf;
}

// ---------------- Phase 3: gather — KCH consecutive output rows per block.
// Each hs row is read exactly once per block; the fire row stays in registers
// and seeds the next segment's residual (resid = alpha[tend] - cur, bit-identical
// to the reference's a - cur).
__global__ void k_gather(const float* __restrict__ hs,
                         float* __restrict__ out) {
    int b   = blockIdx.y;
    int k0  = blockIdx.x * KCH;
    int tid = threadIdx.x;            // 256 threads, 4 floats each
    const int base = b * TT;

    int nf = g_nf[b];
    const float4 zero = make_float4(0.f, 0.f, 0.f, 0.f);

    if (k0 >= nf) {
#pragma unroll
        for (int k = k0; k < k0 + KCH; k++)
            reinterpret_cast<float4*>(out + ((size_t)(base + k)) * DD)[tid] = zero;
        return;
    }

    int klast = (k0 + KCH < nf) ? (k0 + KCH) : nf;

    float4 acc = zero;
    int tprev = -1;

    if (k0 > 0) {
        float2 evp = g_ev[base + k0 - 1];
        tprev = __float_as_int(evp.y);
        float r = g_alphas[base + tprev] - evp.x;   // resid = a - cur
        const float4* h = reinterpret_cast<const float4*>(hs + ((size_t)(base + tprev)) * DD);
        float4 v = h[tid];
        acc.x = r * v.x; acc.y = r * v.y; acc.z = r * v.z; acc.w = r * v.w;
    }

    for (int k = k0; k < klast; k++) {
        float2 ev = g_ev[base + k];
        int tend = __float_as_int(ev.y);

        // interior rows: coefficient == alpha
        for (int t = tprev + 1; t < tend; t++) {
            float c = g_alphas[base + t];
            const float4* h = reinterpret_cast<const float4*>(hs + ((size_t)(base + t)) * DD);
            float4 v = h[tid];
            acc.x = fmaf(c, v.x, acc.x);
            acc.y = fmaf(c, v.y, acc.y);
            acc.z = fmaf(c, v.z, acc.z);
            acc.w = fmaf(c, v.w, acc.w);
        }

        // fire row: finish this output row, then seed the next with the residual
        const float4* h = reinterpret_cast<const float4*>(hs + ((size_t)(base + tend)) * DD);
        float4 v = h[tid];
        float cur = ev.x;
        acc.x = fmaf(cur, v.x, acc.x);
        acc.y = fmaf(cur, v.y, acc.y);
        acc.z = fmaf(cur, v.z, acc.z);
        acc.w = fmaf(cur, v.w, acc.w);
        reinterpret_cast<float4*>(out + ((size_t)(base + k)) * DD)[tid] = acc;

        float r = g_alphas[base + tend] - cur;      // resid = a - cur
        acc.x = r * v.x; acc.y = r * v.y; acc.z = r * v.z; acc.w = r * v.w;
        tprev = tend;
    }

    for (int k = klast; k < k0 + KCH; k++)
        reinterpret_cast<float4*>(out + ((size_t)(base + k)) * DD)[tid] = zero;
}

extern "C" void kernel_launch(void* const* d_in, const int* in_sizes, int n_in,
                              void* d_out, int out_size) {
    const float* hs   = (const float*)d_in[0];   // [B,T,D]
    const float* mask = (const float*)d_in[1];   // [B,1,T]
    const float* w    = (const float*)d_in[2];   // [D]
    const float* bias = (const float*)d_in[3];   // scalar

    float* out   = (float*)d_out;                           // [B,T,D]
    float* omask = (float*)d_out + (size_t)BB * TT * DD;    // [B,1,T] as 0/1 floats

    // Phase 1: 1 warp per (b,t) row
    {
        int warpsPerBlock = 8;
        int blocks = NROW / warpsPerBlock;  // 4096
        k_alphas<<<blocks, warpsPerBlock * 32>>>(hs, mask, w, bias);
    }
    // Phase 2 (fused): scan + lens + mask, one block per batch
    k_scan<<<BB, 256>>>(omask);
    // Phase 3: KCH output rows per block
    {
        dim3 grid(TT / KCH, BB);
        k_gather<<<grid, 256>>>(hs, out);
    }
}

// round 9
// speedup vs baseline: 1.8244x; 1.0027x over previous
#include <cuda_runtime.h>
#include <math.h>

// Problem shape (fixed for this benchmark instance)
#define BB 16
#define TT 2048
#define DD 1024
#define NROW (BB*TT)
#define KCH 4              // output rows per gather block

// Scratch (device globals; no allocation allowed)
__device__ float  g_alphas[NROW];
__device__ float2 g_ev[NROW];       // {dist(=cur at fire), t_as_int_bits} per fire, packed
__device__ int    g_nf[BB];
__device__ int    g_cnt[BB * 32];   // one counter per 128B line; self-resetting

// ---------------- Fused phase 1+2: alphas for 8 rows per block; the LAST block
// of each batch (elected by atomic counter) additionally runs the serial
// integrate-and-fire scan + length/mask for that batch.
// Fire arithmetic bit-identical to the reference:
//   s = integ + a; fire = s > 0.95f;
//   cur = fire ? (1 - integ) : a; integ = fire ? s - 1.0f : s  (Sterbenz-exact)
__global__ void __launch_bounds__(256) k_fused(const float* __restrict__ hs,
                                               const float* __restrict__ mask,
                                               const float* __restrict__ w,
                                               const float* __restrict__ bias,
                                               float* __restrict__ omask) {
    __shared__ float  s_al[TT];      // 8 KB   (scan role)
    __shared__ float2 s_ev[TT];      // 16 KB  (scan role)
    __shared__ double s_part[256];   // 2 KB   (scan role)
    __shared__ int    s_last;
    __shared__ int    s_nf;
    __shared__ int    s_len;

    const int bid  = blockIdx.x;     // 0..4095; 256 blocks per batch, batch-aligned
    const int tid  = threadIdx.x;
    const int wid  = tid >> 5;
    const int lane = tid & 31;
    const int b    = bid >> 8;

    // ---- alphas for this block's 8 rows (one row per warp) ----
    {
        int row = bid * 8 + wid;
        const float4* r4 = reinterpret_cast<const float4*>(hs + (size_t)row * DD);
        const float4* w4 = reinterpret_cast<const float4*>(w);

        float acc = 0.0f;
#pragma unroll
        for (int i = 0; i < 8; i++) {
            float4 h  = r4[lane + 32 * i];
            float4 ww = __ldg(&w4[lane + 32 * i]);
            acc = fmaf(h.x, ww.x, acc);
            acc = fmaf(h.y, ww.y, acc);
            acc = fmaf(h.z, ww.z, acc);
            acc = fmaf(h.w, ww.w, acc);
        }
#pragma unroll
        for (int o = 16; o > 0; o >>= 1)
            acc += __shfl_down_sync(0xffffffffu, acc, o);

        if (lane == 0) {
            float x = acc + bias[0];
            float s = 1.0f / (1.0f + expf(-x));
            g_alphas[row] = s * mask[row];
        }
    }
    __syncthreads();

    // ---- elect the last-arriving block of this batch ----
    if (tid == 0) {
        __threadfence();                                   // release our alphas
        int old = atomicAdd(&g_cnt[b * 32], 1);
        s_last = (old == 255);
    }
    __syncthreads();
    if (!s_last) return;
    if (tid == 0) __threadfence();                         // acquire others' alphas
    __syncthreads();

    // ================= scan role (elected block only) =================
    const float4* al4 = reinterpret_cast<const float4*>(g_alphas + b * TT);
    float4* s4 = reinterpret_cast<float4*>(s_al);
    double psum = 0.0;
#pragma unroll
    for (int i = 0; i < 2; i++) {
        int idx = tid + i * 256;
        float4 v = al4[idx];
        s4[idx] = v;
        psum += (double)v.x + v.y + v.z + v.w;
    }
    s_part[tid] = psum;
    __syncthreads();

    if (wid == 0) {
        if (tid == 0) {
            // -------- serial integrate-and-fire scan (from smem) --------
            float integ = 0.0f;
            int nf = 0;
            float4 p = s4[0];
            for (int t0 = 0; t0 < TT; t0 += 4) {
                float buf[4];
                buf[0] = p.x; buf[1] = p.y; buf[2] = p.z; buf[3] = p.w;
                if (t0 + 4 < TT) p = s4[(t0 >> 2) + 1];
#pragma unroll
                for (int j = 0; j < 4; j++) {
                    float a = buf[j];
                    float dist = 1.0f - integ;      // off critical path
                    float s = integ + a;            // FADD — critical
                    bool fire = (s > 0.95f);        // FSETP — critical
                    float2 e;
                    e.x = dist;                     // cur at fire
                    e.y = __int_as_float(t0 + j);   // fire time index
                    s_ev[nf] = e;                   // unconditional STS.64
                    nf += fire ? 1 : 0;
                    integ = fire ? (s - 1.0f) : s;  // FSEL — critical
                }
            }
            s_nf = nf;
        }
    } else {
        if (wid == 1) {
            // -------- length reduction (concurrent with scan) --------
            double r = s_part[lane]       + s_part[lane + 32]
                     + s_part[lane + 64]  + s_part[lane + 96]
                     + s_part[lane + 128] + s_part[lane + 160]
                     + s_part[lane + 192] + s_part[lane + 224];
#pragma unroll
            for (int o = 16; o > 0; o >>= 1)
                r += __shfl_down_sync(0xffffffffu, r, o);
            if (lane == 0) {
                float fsum = (float)r;
                s_len = (int)rintf(fsum);   // round-half-to-even like jnp.round
            }
        }
        // warps 1-7 sync among themselves; write mask while warp 0 scans
        asm volatile("bar.sync 1, 224;" ::: "memory");
        int len = s_len;
        float4* om4 = reinterpret_cast<float4*>(omask + b * TT);
        for (int i = tid - 32; i < TT / 4; i += 224) {
            int k = i * 4;
            float4 m;
            m.x = (k + 0 < len) ? 1.0f : 0.0f;
            m.y = (k + 1 < len) ? 1.0f : 0.0f;
            m.z = (k + 2 < len) ? 1.0f : 0.0f;
            m.w = (k + 3 < len) ? 1.0f : 0.0f;
            om4[i] = m;
        }
    }
    __syncthreads();

    // -------- coalesced event flush + counter self-reset --------
    int nf = s_nf;
    float2* ev = g_ev + b * TT;
    for (int i = tid; i < nf; i += 256)
        ev[i] = s_ev[i];
    if (tid == 0) {
        g_nf[b] = nf;
        g_cnt[b * 32] = 0;    // ready for next graph replay
    }
}

// ---------------- Phase 3: gather — KCH consecutive output rows per block.
// Each hs row is read once per block; fire rows stay in registers and seed the
// next segment's residual (resid = alpha[tend] - cur, bit-identical to a - cur).
__global__ void k_gather(const float* __restrict__ hs,
                         float* __restrict__ out) {
    int b   = blockIdx.y;
    int k0  = blockIdx.x * KCH;
    int tid = threadIdx.x;            // 256 threads, 4 floats each
    const int base = b * TT;

    int nf = g_nf[b];
    const float4 zero = make_float4(0.f, 0.f, 0.f, 0.f);

    if (k0 >= nf) {
#pragma unroll
        for (int k = k0; k < k0 + KCH; k++)
            reinterpret_cast<float4*>(out + ((size_t)(base + k)) * DD)[tid] = zero;
        return;
    }

    int klast = (k0 + KCH < nf) ? (k0 + KCH) : nf;

    float4 acc = zero;
    int tprev = -1;

    if (k0 > 0) {
        float2 evp = g_ev[base + k0 - 1];
        tprev = __float_as_int(evp.y);
        float r = g_alphas[base + tprev] - evp.x;   // resid = a - cur
        const float4* h = reinterpret_cast<const float4*>(hs + ((size_t)(base + tprev)) * DD);
        float4 v = h[tid];
        acc.x = r * v.x; acc.y = r * v.y; acc.z = r * v.z; acc.w = r * v.w;
    }

    for (int k = k0; k < klast; k++) {
        float2 ev = g_ev[base + k];
        int tend = __float_as_int(ev.y);

        // interior rows: coefficient == alpha
        for (int t = tprev + 1; t < tend; t++) {
            float c = g_alphas[base + t];
            const float4* h = reinterpret_cast<const float4*>(hs + ((size_t)(base + t)) * DD);
            float4 v = h[tid];
            acc.x = fmaf(c, v.x, acc.x);
            acc.y = fmaf(c, v.y, acc.y);
            acc.z = fmaf(c, v.z, acc.z);
            acc.w = fmaf(c, v.w, acc.w);
        }

        // fire row: finish this output row, then seed the next with the residual
        const float4* h = reinterpret_cast<const float4*>(hs + ((size_t)(base + tend)) * DD);
        float4 v = h[tid];
        float cur = ev.x;
        acc.x = fmaf(cur, v.x, acc.x);
        acc.y = fmaf(cur, v.y, acc.y);
        acc.z = fmaf(cur, v.z, acc.z);
        acc.w = fmaf(cur, v.w, acc.w);
        reinterpret_cast<float4*>(out + ((size_t)(base + k)) * DD)[tid] = acc;

        float r = g_alphas[base + tend] - cur;      // resid = a - cur
        acc.x = r * v.x; acc.y = r * v.y; acc.z = r * v.z; acc.w = r * v.w;
        tprev = tend;
    }

    for (int k = klast; k < k0 + KCH; k++)
        reinterpret_cast<float4*>(out + ((size_t)(base + k)) * DD)[tid] = zero;
}

extern "C" void kernel_launch(void* const* d_in, const int* in_sizes, int n_in,
                              void* d_out, int out_size) {
    const float* hs   = (const float*)d_in[0];   // [B,T,D]
    const float* mask = (const float*)d_in[1];   // [B,1,T]
    const float* w    = (const float*)d_in[2];   // [D]
    const float* bias = (const float*)d_in[3];   // scalar

    float* out   = (float*)d_out;                           // [B,T,D]
    float* omask = (float*)d_out + (size_t)BB * TT * DD;    // [B,1,T] as 0/1 floats

    // Fused phase 1+2: alphas + elected per-batch scan/lens/mask
    k_fused<<<NROW / 8, 256>>>(hs, mask, w, bias, omask);
    // Phase 3: KCH output rows per block
    {
        dim3 grid(TT / KCH, BB);
        k_gather<<<grid, 256>>>(hs, out);
    }
}

// round 11
// speedup vs baseline: 2.0752x; 1.1375x over previous
#include <cuda_runtime.h>
#include <math.h>

// Problem shape (fixed for this benchmark instance)
#define BB 16
#define TT 2048
#define DD 1024
#define NROW (BB*TT)
#define KCH 4              // output rows per gather block

// Scratch (device globals; no allocation allowed)
__device__ float  g_alphas[NROW];
__device__ float2 g_ev[NROW];       // {dist(=cur at fire), t_as_int_bits} per fire, packed
__device__ int    g_nf[BB];
__device__ int    g_cnt[BB * 32];   // one counter per 128B line; self-resetting

// ---------------- Fused phase 1+2: alphas for 8 rows per block; the LAST block
// of each batch (elected by atomic counter) additionally runs the serial
// integrate-and-fire scan + length/mask for that batch.
// Fire arithmetic bit-identical to the reference:
//   s = integ + a; fire = s > 0.95f;
//   cur = fire ? (1 - integ) : a; integ = fire ? s - 1.0f : s
// (select implemented as integ = fma(f, -1, s), f in {0,1}: exact same values)
__global__ void __launch_bounds__(256) k_fused(const float* __restrict__ hs,
                                               const float* __restrict__ mask,
                                               const float* __restrict__ w,
                                               const float* __restrict__ bias,
                                               float* __restrict__ omask) {
    __shared__ float  s_al[TT];      // 8 KB   (scan role)
    __shared__ float2 s_ev[TT];      // 16 KB  (scan role)
    __shared__ double s_part[256];   // 2 KB   (scan role)
    __shared__ int    s_last;
    __shared__ int    s_nf;
    __shared__ int    s_len;

    const int bid  = blockIdx.x;     // 0..4095; 256 blocks per batch, batch-aligned
    const int tid  = threadIdx.x;
    const int wid  = tid >> 5;
    const int lane = tid & 31;
    const int b    = bid >> 8;

    // ---- alphas for this block's 8 rows (one row per warp) ----
    {
        int row = bid * 8 + wid;
        const float4* r4 = reinterpret_cast<const float4*>(hs + (size_t)row * DD);
        const float4* w4 = reinterpret_cast<const float4*>(w);

        float acc = 0.0f;
#pragma unroll
        for (int i = 0; i < 8; i++) {
            float4 h  = r4[lane + 32 * i];
            float4 ww = __ldg(&w4[lane + 32 * i]);
            acc = fmaf(h.x, ww.x, acc);
            acc = fmaf(h.y, ww.y, acc);
            acc = fmaf(h.z, ww.z, acc);
            acc = fmaf(h.w, ww.w, acc);
        }
#pragma unroll
        for (int o = 16; o > 0; o >>= 1)
            acc += __shfl_down_sync(0xffffffffu, acc, o);

        if (lane == 0) {
            float x = acc + bias[0];
            float s = 1.0f / (1.0f + expf(-x));
            g_alphas[row] = s * mask[row];
        }
    }
    __syncthreads();

    // ---- elect the last-arriving block of this batch ----
    if (tid == 0) {
        __threadfence();                                   // release our alphas
        int old = atomicAdd(&g_cnt[b * 32], 1);
        s_last = (old == 255);
    }
    __syncthreads();
    if (!s_last) return;
    if (tid == 0) __threadfence();                         // acquire others' alphas
    __syncthreads();

    // ================= scan role (elected block only) =================
    const float4* al4 = reinterpret_cast<const float4*>(g_alphas + b * TT);
    float4* s4 = reinterpret_cast<float4*>(s_al);
    double psum = 0.0;
#pragma unroll
    for (int i = 0; i < 2; i++) {
        int idx = tid + i * 256;
        float4 v = al4[idx];
        s4[idx] = v;
        psum += (double)v.x + v.y + v.z + v.w;
    }
    s_part[tid] = psum;
    __syncthreads();

    if (wid == 0) {
        if (tid == 0) {
            // -------- serial integrate-and-fire scan (from smem) --------
            float integ = 0.0f;
            int nf = 0;
            float4 pa = s4[0], pb = s4[1];
            for (int t0 = 0; t0 < TT; t0 += 8) {
                float buf[8];
                buf[0] = pa.x; buf[1] = pa.y; buf[2] = pa.z; buf[3] = pa.w;
                buf[4] = pb.x; buf[5] = pb.y; buf[6] = pb.z; buf[7] = pb.w;
                if (t0 + 8 < TT) {
                    pa = s4[(t0 >> 2) + 2];
                    pb = s4[(t0 >> 2) + 3];
                }
#pragma unroll
                for (int j = 0; j < 8; j++) {
                    float a = buf[j];
                    float dist = 1.0f - integ;          // off critical path
                    float s = integ + a;                // FADD — critical
                    bool fire = (s > 0.95f);            // FSETP — critical
                    float f = fire ? 1.0f : 0.0f;       // SEL (pred-as-data) — critical
                    float2 e;
                    e.x = dist;                         // cur at fire
                    e.y = __int_as_float(t0 + j);       // fire time index
                    s_ev[nf] = e;                       // unconditional STS.64
                    nf += fire ? 1 : 0;
                    integ = fmaf(f, -1.0f, s);          // FFMA — critical (exact s or s-1)
                }
            }
            s_nf = nf;
        }
    } else {
        if (wid == 1) {
            // -------- length reduction (concurrent with scan) --------
            double r = s_part[lane]       + s_part[lane + 32]
                     + s_part[lane + 64]  + s_part[lane + 96]
                     + s_part[lane + 128] + s_part[lane + 160]
                     + s_part[lane + 192] + s_part[lane + 224];
#pragma unroll
            for (int o = 16; o > 0; o >>= 1)
                r += __shfl_down_sync(0xffffffffu, r, o);
            if (lane == 0) {
                float fsum = (float)r;
                s_len = (int)rintf(fsum);   // round-half-to-even like jnp.round
            }
        }
        // warps 1-7 sync among themselves; write mask while warp 0 scans
        asm volatile("bar.sync 1, 224;" ::: "memory");
        int len = s_len;
        float4* om4 = reinterpret_cast<float4*>(omask + b * TT);
        for (int i = tid - 32; i < TT / 4; i += 224) {
            int k = i * 4;
            float4 m;
            m.x = (k + 0 < len) ? 1.0f : 0.0f;
            m.y = (k + 1 < len) ? 1.0f : 0.0f;
            m.z = (k + 2 < len) ? 1.0f : 0.0f;
            m.w = (k + 3 < len) ? 1.0f : 0.0f;
            om4[i] = m;
        }
    }
    __syncthreads();

    // -------- coalesced event flush + counter self-reset --------
    int nf = s_nf;
    float2* ev = g_ev + b * TT;
    for (int i = tid; i < nf; i += 256)
        ev[i] = s_ev[i];
    if (tid == 0) {
        g_nf[b] = nf;
        g_cnt[b * 32] = 0;    // ready for next graph replay
    }
}

// ---------------- Phase 3: gather — KCH consecutive output rows per block.
// Block->work mapping is REVERSED (first-scheduled blocks take the last batch
// and highest k) so gather's hs reads start on the rows most recently touched
// by k_fused — i.e. the ones still resident in L2.
__global__ void k_gather(const float* __restrict__ hs,
                         float* __restrict__ out) {
    int b   = (BB - 1) - blockIdx.y;                    // reversed batch order
    int k0  = (TT / KCH - 1 - blockIdx.x) * KCH;        // reversed k order
    int tid = threadIdx.x;            // 256 threads, 4 floats each
    const int base = b * TT;

    int nf = g_nf[b];
    const float4 zero = make_float4(0.f, 0.f, 0.f, 0.f);

    if (k0 >= nf) {
#pragma unroll
        for (int k = k0; k < k0 + KCH; k++)
            reinterpret_cast<float4*>(out + ((size_t)(base + k)) * DD)[tid] = zero;
        return;
    }

    int klast = (k0 + KCH < nf) ? (k0 + KCH) : nf;

    float4 acc = zero;
    int tprev = -1;

    if (k0 > 0) {
        float2 evp = g_ev[base + k0 - 1];
        tprev = __float_as_int(evp.y);
        float r = g_alphas[base + tprev] - evp.x;   // resid = a - cur
        const float4* h = reinterpret_cast<const float4*>(hs + ((size_t)(base + tprev)) * DD);
        float4 v = h[tid];
        acc.x = r * v.x; acc.y = r * v.y; acc.z = r * v.z; acc.w = r * v.w;
    }

    for (int k = k0; k < klast; k++) {
        float2 ev = g_ev[base + k];
        int tend = __float_as_int(ev.y);

        // interior rows: coefficient == alpha
        for (int t = tprev + 1; t < tend; t++) {
            float c = g_alphas[base + t];
            const float4* h = reinterpret_cast<const float4*>(hs + ((size_t)(base + t)) * DD);
            float4 v = h[tid];
            acc.x = fmaf(c, v.x, acc.x);
            acc.y = fmaf(c, v.y, acc.y);
            acc.z = fmaf(c, v.z, acc.z);
            acc.w = fmaf(c, v.w, acc.w);
        }

        // fire row: finish this output row, then seed the next with the residual
        const float4* h = reinterpret_cast<const float4*>(hs + ((size_t)(base + tend)) * DD);
        float4 v = h[tid];
        float cur = ev.x;
        acc.x = fmaf(cur, v.x, acc.x);
        acc.y = fmaf(cur, v.y, acc.y);
        acc.z = fmaf(cur, v.z, acc.z);
        acc.w = fmaf(cur, v.w, acc.w);
        reinterpret_cast<float4*>(out + ((size_t)(base + k)) * DD)[tid] = acc;

        float r = g_alphas[base + tend] - cur;      // resid = a - cur
        acc.x = r * v.x; acc.y = r * v.y; acc.z = r * v.z; acc.w = r * v.w;
        tprev = tend;
    }

    for (int k = klast; k < k0 + KCH; k++)
        reinterpret_cast<float4*>(out + ((size_t)(base + k)) * DD)[tid] = zero;
}

extern "C" void kernel_launch(void* const* d_in, const int* in_sizes, int n_in,
                              void* d_out, int out_size) {
    const float* hs   = (const float*)d_in[0];   // [B,T,D]
    const float* mask = (const float*)d_in[1];   // [B,1,T]
    const float* w    = (const float*)d_in[2];   // [D]
    const float* bias = (const float*)d_in[3];   // scalar

    float* out   = (float*)d_out;                           // [B,T,D]
    float* omask = (float*)d_out + (size_t)BB * TT * DD;    // [B,1,T] as 0/1 floats

    // Fused phase 1+2: alphas + elected per-batch scan/lens/mask
    k_fused<<<NROW / 8, 256>>>(hs, mask, w, bias, omask);
    // Phase 3: KCH output rows per block, reverse-ordered for L2 reuse
    {
        dim3 grid(TT / KCH, BB);
        k_gather<<<grid, 256>>>(hs, out);
    }
}

// round 13
// speedup vs baseline: 2.1994x; 1.0599x over previous
#include <cuda_runtime.h>
#include <math.h>

// Problem shape (fixed for this benchmark instance)
#define BB 16
#define TT 2048
#define DD 1024
#define NROW (BB*TT)
#define KCH 4              // output rows per gather block
#define NCH 4              // scan segments per batch
#define CHT (TT/NCH)       // 512 timesteps per segment
#define CBLK 64            // alpha blocks per (batch, chunk): 512 rows / 8

// Scratch (device globals; no allocation allowed)
__device__ float  g_alphas[NROW];
__device__ float2 g_ev[NROW];             // {cur, t_bits} per fire, packed per batch
__device__ int    g_nf[BB];
__device__ float2 g_carry[BB * NCH];      // {integ, nf_bits} after segment c
__device__ double g_psum[BB * NCH];       // per-segment alpha sums
__device__ int    g_cnt[BB * NCH * 32];   // one counter per 128B line; self-resetting

// ---------------- Fused: alphas (t-chunk-major) + chained elected scan segments.
// Election rule: slot (b,c) needs 64 alpha arrivals (+1 carry arrival for c>0);
// the LAST arriver — alpha block or predecessor runner — executes the segment.
// Fire arithmetic bit-identical to the reference:
//   s = integ + a; fire = s > 0.95f;
//   cur = fire ? (1 - integ) : a; integ = fire ? s - 1.0f : s
// (select as integ = fma(f, -1, s), f in {0,1}: exact same values)
__global__ void __launch_bounds__(256) k_fused(const float* __restrict__ hs,
                                               const float* __restrict__ mask,
                                               const float* __restrict__ w,
                                               const float* __restrict__ bias,
                                               float* __restrict__ omask) {
    __shared__ float  s_al[CHT];          // 2 KB
    __shared__ float2 s_ev[CHT];          // 4 KB
    __shared__ double s_part[128];        // 1 KB
    __shared__ float2 s_carry;
    __shared__ int    s_elected;
    __shared__ int    s_nf;
    __shared__ int    s_len;

    const int bid  = blockIdx.x;          // 4096 blocks: chunk-major
    const int tid  = threadIdx.x;
    const int wid  = tid >> 5;
    const int lane = tid & 31;

    const int chunk  = bid >> 10;         // 1024 blocks per chunk
    const int within = bid & 1023;
    const int b      = within >> 6;       // 64 blocks per (batch, chunk)
    const int tblk   = within & 63;

    // ---- alphas for this block's 8 rows (one row per warp) ----
    {
        int row = b * TT + chunk * CHT + tblk * 8 + wid;
        const float4* r4 = reinterpret_cast<const float4*>(hs + (size_t)row * DD);
        const float4* w4 = reinterpret_cast<const float4*>(w);

        float acc = 0.0f;
#pragma unroll
        for (int i = 0; i < 8; i++) {
            float4 h  = r4[lane + 32 * i];
            float4 ww = __ldg(&w4[lane + 32 * i]);
            acc = fmaf(h.x, ww.x, acc);
            acc = fmaf(h.y, ww.y, acc);
            acc = fmaf(h.z, ww.z, acc);
            acc = fmaf(h.w, ww.w, acc);
        }
#pragma unroll
        for (int o = 16; o > 0; o >>= 1)
            acc += __shfl_down_sync(0xffffffffu, acc, o);

        if (lane == 0) {
            float x = acc + bias[0];
            float s = 1.0f / (1.0f + expf(-x));
            g_alphas[row] = s * mask[row];
        }
    }
    __syncthreads();

    // ---- initial election: last arriver on this (b, chunk) slot ----
    if (tid == 0) {
        __threadfence();                               // release our alphas
        int need = (chunk == 0) ? (CBLK - 1) : CBLK;   // 64th / 65th arrival wins
        int old = atomicAdd(&g_cnt[(b * NCH + chunk) * 32], 1);
        s_elected = (old == need);
    }
    __syncthreads();
    if (!s_elected) return;

    // ================= segment-chaining runner =================
    int chunk_run = chunk;
    for (;;) {
        const int slot = b * NCH + chunk_run;

        // acquire producers' writes (alphas, carry, psums)
        if (tid == 0) {
            __threadfence();
            float2 c;
            if (chunk_run > 0) c = g_carry[slot - 1];
            else               c = make_float2(0.0f, __int_as_float(0));
            s_carry = c;
        }
        __syncthreads();
        const float integ0 = s_carry.x;
        const int   nf_in  = __float_as_int(s_carry.y);

        // stage this segment's 512 alphas into smem + per-thread partial sums
        const float4* al4 = reinterpret_cast<const float4*>(g_alphas + b * TT + chunk_run * CHT);
        float4* s4 = reinterpret_cast<float4*>(s_al);
        if (tid < 128) {
            float4 v = al4[tid];
            s4[tid] = v;
            s_part[tid] = (double)v.x + v.y + v.z + v.w;
        }
        __syncthreads();

        if (wid == 0) {
            if (tid == 0) {
                // -------- serial scan of 512 steps (from smem) --------
                float integ = integ0;
                int nfseg = 0;
                float4 pa = s4[0], pb = s4[1];
                for (int t0 = 0; t0 < CHT; t0 += 8) {
                    float buf[8];
                    buf[0] = pa.x; buf[1] = pa.y; buf[2] = pa.z; buf[3] = pa.w;
                    buf[4] = pb.x; buf[5] = pb.y; buf[6] = pb.z; buf[7] = pb.w;
                    if (t0 + 8 < CHT) {
                        pa = s4[(t0 >> 2) + 2];
                        pb = s4[(t0 >> 2) + 3];
                    }
#pragma unroll
                    for (int j = 0; j < 8; j++) {
                        float a = buf[j];
                        float dist = 1.0f - integ;          // off critical path
                        float s = integ + a;                // FADD — critical
                        bool fire = (s > 0.95f);            // FSETP — critical
                        float f = fire ? 1.0f : 0.0f;       // SEL — critical
                        float2 e;
                        e.x = dist;                                       // cur at fire
                        e.y = __int_as_float(chunk_run * CHT + t0 + j);   // fire time
                        s_ev[nfseg] = e;                                  // STS.64
                        nfseg += fire ? 1 : 0;
                        integ = fmaf(f, -1.0f, s);          // FFMA — critical (exact)
                    }
                }
                s_nf = nfseg;
                s_carry.x = integ;                          // pass out to epilogue
            }
        } else {
            if (wid == 1) {
                // segment partial sum (concurrent with scan)
                double r = s_part[lane] + s_part[lane + 32]
                         + s_part[lane + 64] + s_part[lane + 96];
#pragma unroll
                for (int o = 16; o > 0; o >>= 1)
                    r += __shfl_down_sync(0xffffffffu, r, o);
                if (lane == 0) {
                    g_psum[slot] = r;
                    if (chunk_run == NCH - 1) {
                        double tot = g_psum[b * NCH + 0] + g_psum[b * NCH + 1]
                                   + g_psum[b * NCH + 2] + r;
                        float fsum = (float)tot;
                        s_len = (int)rintf(fsum);   // round-half-to-even like jnp.round
                    }
                }
            }
            if (chunk_run == NCH - 1) {
                // warps 1-7 sync among themselves; write mask while warp 0 scans
                asm volatile("bar.sync 1, 224;" ::: "memory");
                int len = s_len;
                float4* om4 = reinterpret_cast<float4*>(omask + b * TT);
                for (int i = tid - 32; i < TT / 4; i += 224) {
                    int k = i * 4;
                    float4 m;
                    m.x = (k + 0 < len) ? 1.0f : 0.0f;
                    m.y = (k + 1 < len) ? 1.0f : 0.0f;
                    m.z = (k + 2 < len) ? 1.0f : 0.0f;
                    m.w = (k + 3 < len) ? 1.0f : 0.0f;
                    om4[i] = m;
                }
            }
        }
        __syncthreads();

        // -------- coalesced event flush at offset nf_in --------
        const int nf = s_nf;
        float2* ev = g_ev + b * TT + nf_in;
        for (int i = tid; i < nf; i += 256)
            ev[i] = s_ev[i];
        __syncthreads();

        // -------- epilogue: carry hand-off + (possible) self-election --------
        if (tid == 0) {
            if (chunk_run < NCH - 1) {
                float2 carry;
                carry.x = s_carry.x;                       // final integ of this segment
                carry.y = __int_as_float(nf_in + nf);
                g_carry[slot] = carry;
                __threadfence();                           // release carry+events+psum
                int old = atomicAdd(&g_cnt[(slot + 1) * 32], 1);
                s_elected = (old == CBLK);                 // 65th arrival wins
            } else {
                g_nf[b] = nf_in + nf;
                s_elected = 0;
            }
            g_cnt[slot * 32] = 0;                          // self-reset (all arrivals done)
        }
        __syncthreads();
        if (!s_elected) return;
        chunk_run++;
    }
}

// ---------------- Phase 3: gather — KCH consecutive output rows per block.
// Reverse-ordered so first-scheduled blocks read the hs rows most recently
// touched by k_fused (still L2-resident).
__global__ void k_gather(const float* __restrict__ hs,
                         float* __restrict__ out) {
    int b   = (BB - 1) - blockIdx.y;                    // reversed batch order
    int k0  = (TT / KCH - 1 - blockIdx.x) * KCH;        // reversed k order
    int tid = threadIdx.x;            // 256 threads, 4 floats each
    const int base = b * TT;

    int nf = g_nf[b];
    const float4 zero = make_float4(0.f, 0.f, 0.f, 0.f);

    if (k0 >= nf) {
#pragma unroll
        for (int k = k0; k < k0 + KCH; k++)
            reinterpret_cast<float4*>(out + ((size_t)(base + k)) * DD)[tid] = zero;
        return;
    }

    int klast = (k0 + KCH < nf) ? (k0 + KCH) : nf;

    float4 acc = zero;
    int tprev = -1;

    if (k0 > 0) {
        float2 evp = g_ev[base + k0 - 1];
        tprev = __float_as_int(evp.y);
        float r = g_alphas[base + tprev] - evp.x;   // resid = a - cur
        const float4* h = reinterpret_cast<const float4*>(hs + ((size_t)(base + tprev)) * DD);
        float4 v = h[tid];
        acc.x = r * v.x; acc.y = r * v.y; acc.z = r * v.z; acc.w = r * v.w;
    }

    for (int k = k0; k < klast; k++) {
        float2 ev = g_ev[base + k];
        int tend = __float_as_int(ev.y);

        // interior rows: coefficient == alpha
        for (int t = tprev + 1; t < tend; t++) {
            float c = g_alphas[base + t];
            const float4* h = reinterpret_cast<const float4*>(hs + ((size_t)(base + t)) * DD);
            float4 v = h[tid];
            acc.x = fmaf(c, v.x, acc.x);
            acc.y = fmaf(c, v.y, acc.y);
            acc.z = fmaf(c, v.z, acc.z);
            acc.w = fmaf(c, v.w, acc.w);
        }

        // fire row: finish this output row, then seed the next with the residual
        const float4* h = reinterpret_cast<const float4*>(hs + ((size_t)(base + tend)) * DD);
        float4 v = h[tid];
        float cur = ev.x;
        acc.x = fmaf(cur, v.x, acc.x);
        acc.y = fmaf(cur, v.y, acc.y);
        acc.z = fmaf(cur, v.z, acc.z);
        acc.w = fmaf(cur, v.w, acc.w);
        reinterpret_cast<float4*>(out + ((size_t)(base + k)) * DD)[tid] = acc;

        float r = g_alphas[base + tend] - cur;      // resid = a - cur
        acc.x = r * v.x; acc.y = r * v.y; acc.z = r * v.z; acc.w = r * v.w;
        tprev = tend;
    }

    for (int k = klast; k < k0 + KCH; k++)
        reinterpret_cast<float4*>(out + ((size_t)(base + k)) * DD)[tid] = zero;
}

extern "C" void kernel_launch(void* const* d_in, const int* in_sizes, int n_in,
                              void* d_out, int out_size) {
    const float* hs   = (const float*)d_in[0];   // [B,T,D]
    const float* mask = (const float*)d_in[1];   // [B,1,T]
    const float* w    = (const float*)d_in[2];   // [D]
    const float* bias = (const float*)d_in[3];   // scalar

    float* out   = (float*)d_out;                           // [B,T,D]
    float* omask = (float*)d_out + (size_t)BB * TT * DD;    // [B,1,T] as 0/1 floats

    // Fused: alphas (t-chunk-major) + chained scan segments + lens/mask
    k_fused<<<NROW / 8, 256>>>(hs, mask, w, bias, omask);
    // Phase 3: KCH output rows per block, reverse-ordered for L2 reuse
    {
        dim3 grid(TT / KCH, BB);
        k_gather<<<grid, 256>>>(hs, out);
    }
}